// round 2
// baseline (speedup 1.0000x reference)
#include <cuda_runtime.h>

#define NB    8
#define PPC   1024
#define NPTS  8192
#define KNN   20
#define NEDGE (NPTS*KNN)

// ---------------- scratch (device globals; allocation-free) ----------------
__device__ int   g_nbr[NEDGE];
__device__ float g_h1[NEDGE*64];          // layer1 out
__device__ float g_y2[NEDGE*128];         // layer2 out (pre-max)
__device__ float g_x1[NPTS*128];          // after max over K
__device__ float g_x3[NPTS*1024];         // layer3 out
__device__ float g_xg[NB*2048];           // pooled [max | mean]
__device__ float g_Bp1[60*64];            // packed coeffs [f][o]
__device__ float g_Bp2[1120*128];
__device__ float g_Bp3[2240*1024];
__device__ float g_Bp4[38400*40];
__device__ float g_l4p[NB*8*40];          // layer4 partials

// ---------------- coefficient repack: src (2,dout,nw,W,g) -> dst [f][o] ----
// f = ((w*W+i)*g + k)*2 + trig
__global__ void pack_coef(const float* __restrict__ src, int which,
                          int dout, int nw, int W, int total) {
    float* dst = (which == 0) ? g_Bp1 : (which == 1) ? g_Bp2
               : (which == 2) ? g_Bp3 : g_Bp4;
    const int g = 5;
    for (int idx = blockIdx.x * blockDim.x + threadIdx.x; idx < total;
         idx += gridDim.x * blockDim.x) {
        int o = idx % dout;
        int f = idx / dout;
        int trig = f & 1;
        int f2 = f >> 1;
        int k = f2 % g;
        int wi = f2 / g;
        int w = wi / W;
        int i = wi - w * W;
        dst[idx] = src[((((trig * dout) + o) * nw + w) * W + i) * g + k];
    }
}

// ---------------- kNN: register top-20 per query thread ----------------
__global__ void knn_kernel(const float* __restrict__ pos) {
    __shared__ float sx[PPC], sy[PPC], sz[PPC];
    int tid = threadIdx.x;                   // 256
    int b   = blockIdx.x >> 2;               // 32 blocks = 8 clouds x 4
    int ql  = ((blockIdx.x & 3) << 8) + tid; // local query index 0..1023
    for (int p = tid; p < PPC; p += 256) {
        const float* pp = pos + (b * PPC + p) * 3;
        sx[p] = pp[0]; sy[p] = pp[1]; sz[p] = pp[2];
    }
    __syncthreads();
    float qx = sx[ql], qy = sy[ql], qz = sz[ql];
    float v[KNN]; int id[KNN];
#pragma unroll
    for (int j = 0; j < KNN; ++j) { v[j] = 1e30f; id[j] = -1; }
    float vmax = 1e30f; int mpos = 0;
    for (int p = 0; p < PPC; ++p) {
        float dx = sx[p] - qx, dy = sy[p] - qy, dz = sz[p] - qz;
        float d = dx * dx + dy * dy + dz * dz;
        if (p == ql) d = 1e30f;              // exclude self
        if (d < vmax) {
#pragma unroll
            for (int j = 0; j < KNN; ++j) if (j == mpos) { v[j] = d; id[j] = p; }
            vmax = v[0]; mpos = 0;
#pragma unroll
            for (int j = 1; j < KNN; ++j) if (v[j] > vmax) { vmax = v[j]; mpos = j; }
        }
    }
    int q = b * PPC + ql;
#pragma unroll
    for (int j = 0; j < KNN; ++j) g_nbr[q * KNN + j] = b * PPC + id[j];
}

// ---------------- layer1: edge feats -> 64 channels ----------------
__global__ void layer1_kernel(const float* __restrict__ pos,
                              const float* __restrict__ b1) {
    __shared__ float Cs[60 * 64];
    __shared__ float bs[64];
    int tid = threadIdx.x;                   // 128
    for (int i = tid; i < 60 * 64; i += 128) Cs[i] = g_Bp1[i];
    if (tid < 64) bs[tid] = b1[tid];
    __syncthreads();
    int edge = blockIdx.x * 128 + tid;
    int n = edge / KNN;
    int pj = g_nbr[edge];
    const float* Pi = pos + n * 3;
    const float* Pj = pos + pj * 3;
    float e[6];
    e[0] = Pi[0]; e[1] = Pi[1]; e[2] = Pi[2];
    e[3] = Pj[0] - Pi[0]; e[4] = Pj[1] - Pi[1]; e[5] = Pj[2] - Pi[2];
    float acc[64];
#pragma unroll
    for (int o = 0; o < 64; ++o) acc[o] = bs[o];
#pragma unroll
    for (int d = 0; d < 6; ++d) {
        int i = d % 3;
        float ham = 0.54f - 0.46f * cosf(6.2831853071795864f * (float)i / 2.0f);
        float a = e[d] * ham;
        float s, c; __sincosf(a, &s, &c);
        float ck = c, sk = s;
#pragma unroll
        for (int k = 0; k < 5; ++k) {
            if (k > 0) { float cn = ck * c - sk * s, sn = sk * c + ck * s; ck = cn; sk = sn; }
            int f = (d * 5 + k) * 2;
            const float4* c4 = (const float4*)&Cs[f * 64];
            const float4* s4 = (const float4*)&Cs[(f + 1) * 64];
#pragma unroll
            for (int o4 = 0; o4 < 16; ++o4) {
                float4 cc = c4[o4], ss = s4[o4];
                acc[o4 * 4 + 0] += ck * cc.x + sk * ss.x;
                acc[o4 * 4 + 1] += ck * cc.y + sk * ss.y;
                acc[o4 * 4 + 2] += ck * cc.z + sk * ss.z;
                acc[o4 * 4 + 3] += ck * cc.w + sk * ss.w;
            }
        }
    }
    float4* out4 = (float4*)&g_h1[edge * 64];
#pragma unroll
    for (int o4 = 0; o4 < 16; ++o4)
        out4[o4] = make_float4(acc[o4*4], acc[o4*4+1], acc[o4*4+2], acc[o4*4+3]);
}

// ---------------- fused-basis SGEMM for layers 2 and 3 ----------------
// y[M, DOUT] = Phi(x)[M, NW*W*G*2] @ Bp + bias, basis generated on the fly.
template<int LAYER>
__global__ void __launch_bounds__(256)
kan_gemm(const float* __restrict__ bias) {
    constexpr int DIN  = (LAYER == 2) ? 64 : 128;
    constexpr int W    = (LAYER == 2) ? 16 : 32;
    constexpr int S    = (LAYER == 2) ? 8  : 16;
    constexpr int NW   = 7;
    constexpr int DOUT = (LAYER == 2) ? 128 : 1024;
    constexpr int BM = 128, BK = 10, G = 5;
    const float* x  = (LAYER == 2) ? g_h1 : g_x1;
    const float* Bp = (LAYER == 2) ? g_Bp2 : g_Bp3;
    float*       y  = (LAYER == 2) ? g_y2 : g_x3;

    __shared__ float As[BK][BM];
    __shared__ float Bs[BK][128];
    int m0 = blockIdx.x * BM;
    int n0 = blockIdx.y * 128;
    int tid = threadIdx.x;
    float acc[8][8];
#pragma unroll
    for (int a = 0; a < 8; ++a)
#pragma unroll
        for (int bq = 0; bq < 8; ++bq) acc[a][bq] = 0.f;

    for (int c = 0; c < NW * W; ++c) {
        __syncthreads();
        if (tid < BM) {
            int w = c / W, i = c - w * W;
            int d = w * S + i;
            float ham = 0.54f - 0.46f * cosf(6.2831853071795864f * (float)i / (float)(W - 1));
            float a = x[(m0 + tid) * DIN + d] * ham;
            float s, cc; __sincosf(a, &s, &cc);
            float ck = cc, sk = s;
            As[0][tid] = ck; As[1][tid] = sk;
#pragma unroll
            for (int k = 1; k < G; ++k) {
                float cn = ck * cc - sk * s, sn = sk * cc + ck * s;
                ck = cn; sk = sn;
                As[2 * k][tid] = ck; As[2 * k + 1][tid] = sk;
            }
        } else {
            int o = tid - BM;
            const float* bp = Bp + c * BK * DOUT + n0 + o;
#pragma unroll
            for (int j = 0; j < BK; ++j) Bs[j][o] = bp[j * DOUT];
        }
        __syncthreads();
        int tx = tid & 15, ty = tid >> 4;
#pragma unroll
        for (int j = 0; j < BK; ++j) {
            float4 a0 = *(const float4*)&As[j][ty * 8];
            float4 a1 = *(const float4*)&As[j][ty * 8 + 4];
            float4 b0 = *(const float4*)&Bs[j][tx * 8];
            float4 b1 = *(const float4*)&Bs[j][tx * 8 + 4];
            float av[8] = {a0.x, a0.y, a0.z, a0.w, a1.x, a1.y, a1.z, a1.w};
            float bv[8] = {b0.x, b0.y, b0.z, b0.w, b1.x, b1.y, b1.z, b1.w};
#pragma unroll
            for (int ee = 0; ee < 8; ++ee)
#pragma unroll
                for (int oo = 0; oo < 8; ++oo)
                    acc[ee][oo] += av[ee] * bv[oo];
        }
    }
    int tx = tid & 15, ty = tid >> 4;
    float bv[8];
#pragma unroll
    for (int oo = 0; oo < 8; ++oo) bv[oo] = bias[n0 + tx * 8 + oo];
#pragma unroll
    for (int ee = 0; ee < 8; ++ee) {
        float4 v0 = make_float4(acc[ee][0] + bv[0], acc[ee][1] + bv[1],
                                acc[ee][2] + bv[2], acc[ee][3] + bv[3]);
        float4 v1 = make_float4(acc[ee][4] + bv[4], acc[ee][5] + bv[5],
                                acc[ee][6] + bv[6], acc[ee][7] + bv[7]);
        float4* o4 = (float4*)&y[(m0 + ty * 8 + ee) * DOUT + n0 + tx * 8];
        o4[0] = v0; o4[1] = v1;
    }
}

// ---------------- max over K neighbors ----------------
__global__ void maxagg_kernel() {
    int n = blockIdx.x, c = threadIdx.x;     // 8192 x 128
    const float* p = g_y2 + n * KNN * 128 + c;
    float m = p[0];
#pragma unroll
    for (int j = 1; j < KNN; ++j) m = fmaxf(m, p[j * 128]);
    g_x1[n * 128 + c] = m;
}

// ---------------- segment max + mean pooling ----------------
__global__ void pool_kernel() {
    int b = blockIdx.x;
    int c = blockIdx.y * 128 + threadIdx.x;  // grid (8,8) x 128
    const float* p = g_x3 + b * PPC * 1024 + c;
    float mx = -1e30f, sm = 0.f;
    for (int pt = 0; pt < PPC; ++pt) {
        float v = p[pt * 1024];
        mx = fmaxf(mx, v); sm += v;
    }
    g_xg[b * 2048 + c] = mx;
    g_xg[b * 2048 + 1024 + c] = sm * (1.0f / 1024.0f);
}

// ---------------- layer4 (partial over feature slices) ----------------
__global__ void layer4_part() {
    __shared__ float xs[2048];
    __shared__ float wsum[8][40];
    int b = blockIdx.x, sl = blockIdx.y, tid = threadIdx.x;  // (8,8) x 256
    for (int i = tid; i < 2048; i += 256) xs[i] = g_xg[b * 2048 + i];
    __syncthreads();
    float acc[40];
#pragma unroll
    for (int o = 0; o < 40; ++o) acc[o] = 0.f;
    for (int pp = tid; pp < 480; pp += 256) {
        int p = sl * 480 + pp;               // (w,i) pair index, 15*256 total
        int w = p >> 8, i = p & 255;
        int d = (w << 7) + i;                // w*128 + i
        float ham = 0.54f - 0.46f * cosf(6.2831853071795864f * (float)i / 255.0f);
        float a = xs[d] * ham;
        float s, c; __sincosf(a, &s, &c);
        float ck = c, sk = s;
        const float* bp = g_Bp4 + p * 400;   // 10 rows x 40
#pragma unroll
        for (int k = 0; k < 5; ++k) {
            if (k > 0) { float cn = ck * c - sk * s, sn = sk * c + ck * s; ck = cn; sk = sn; }
            const float* c0 = bp + (2 * k) * 40;
            const float* s0 = bp + (2 * k + 1) * 40;
#pragma unroll
            for (int o = 0; o < 40; ++o) acc[o] += ck * c0[o] + sk * s0[o];
        }
    }
    int lane = tid & 31, wp = tid >> 5;
#pragma unroll
    for (int o = 0; o < 40; ++o) {
        float t = acc[o];
#pragma unroll
        for (int off = 16; off > 0; off >>= 1) t += __shfl_down_sync(0xffffffffu, t, off);
        if (lane == 0) wsum[wp][o] = t;
    }
    __syncthreads();
    if (tid < 40) {
        float t = 0.f;
#pragma unroll
        for (int w8 = 0; w8 < 8; ++w8) t += wsum[w8][tid];
        g_l4p[(b * 8 + sl) * 40 + tid] = t;
    }
}

__global__ void layer4_final(const float* __restrict__ b4, float* __restrict__ out) {
    int t = threadIdx.x;                     // 320
    if (t < 320) {
        int o = t % 40;
        int b = t / 40;
        float s = b4[o];
#pragma unroll
        for (int sl = 0; sl < 8; ++sl) s += g_l4p[(b * 8 + sl) * 40 + o];
        out[t] = s;
    }
}

// ---------------- launch ----------------
extern "C" void kernel_launch(void* const* d_in, const int* in_sizes, int n_in,
                              void* d_out, int out_size) {
    (void)in_sizes; (void)n_in; (void)out_size;
    const float* pos = (const float*)d_in[0];
    const float* c1  = (const float*)d_in[2];
    const float* b1  = (const float*)d_in[3];
    const float* c2  = (const float*)d_in[4];
    const float* b2  = (const float*)d_in[5];
    const float* c3  = (const float*)d_in[6];
    const float* b3  = (const float*)d_in[7];
    const float* c4  = (const float*)d_in[8];
    const float* b4  = (const float*)d_in[9];
    float* out = (float*)d_out;

    pack_coef<<<15,   256>>>(c1, 0, 64,   2, 3,   60 * 64);
    pack_coef<<<560,  256>>>(c2, 1, 128,  7, 16,  1120 * 128);
    pack_coef<<<8960, 256>>>(c3, 2, 1024, 7, 32,  2240 * 1024);
    pack_coef<<<6000, 256>>>(c4, 3, 40,   15, 256, 38400 * 40);

    knn_kernel<<<32, 256>>>(pos);
    layer1_kernel<<<NEDGE / 128, 128>>>(pos, b1);
    kan_gemm<2><<<dim3(NEDGE / 128, 1), 256>>>(b2);
    maxagg_kernel<<<NPTS, 128>>>();
    kan_gemm<3><<<dim3(NPTS / 128, 8), 256>>>(b3);
    pool_kernel<<<dim3(NB, 8), 128>>>();
    layer4_part<<<dim3(NB, 8), 256>>>();
    layer4_final<<<1, 320>>>(b4, out);
}

// round 5
// speedup vs baseline: 1.5481x; 1.5481x over previous
#include <cuda_runtime.h>
#include <cuda_bf16.h>
#include <cstdint>

#define NB    8
#define PPC   1024
#define NPTS  8192
#define KNN   20
#define NEDGE (NPTS*KNN)

// ---------------- scratch (device globals; allocation-free) ----------------
__device__ int   g_nbr[NEDGE];
__device__ __align__(16) float g_h1T[64*NEDGE];    // layer1 out, TRANSPOSED [c][edge]
__device__ __align__(16) float g_y2[NEDGE*128];    // layer2 out (pre-max), row-major
__device__ __align__(16) float g_x1T[128*NPTS];    // after max over K, TRANSPOSED [c][n]
__device__ __align__(16) float g_x3[NPTS*1024];    // layer3 out, row-major
__device__ float g_xg[NB*2048];                    // pooled [max | mean]
__device__ __align__(16) float g_Bp1[60*64];       // layer1 coeffs [f][o]
__device__ __align__(16) float g_Bp4[38400*40];    // layer4 coeffs [f][o]
__device__ __align__(16) __nv_bfloat16 g_B2h[128*1120];   // layer2 coeffs [o][f] hi
__device__ __align__(16) __nv_bfloat16 g_B2l[128*1120];   // lo
__device__ __align__(16) __nv_bfloat16 g_B3h[1024*2240];  // layer3 [o][f] hi
__device__ __align__(16) __nv_bfloat16 g_B3l[1024*2240];  // lo
__device__ float g_l4p[NB*8*40];

// ---------------- fp32 coefficient repack (layers 1,4): (2,dout,nw,W,g) -> [f][o]
// f = ((w*W+i)*g + k)*2 + trig
__global__ void pack_coef(const float* __restrict__ src, int which,
                          int dout, int nw, int W, int total) {
    float* dst = (which == 0) ? g_Bp1 : g_Bp4;
    const int g = 5;
    for (int idx = blockIdx.x * blockDim.x + threadIdx.x; idx < total;
         idx += gridDim.x * blockDim.x) {
        int o = idx % dout;
        int f = idx / dout;
        int trig = f & 1;
        int f2 = f >> 1;
        int k = f2 % g;
        int wi = f2 / g;
        int w = wi / W;
        int i = wi - w * W;
        dst[idx] = src[((((trig * dout) + o) * nw + w) * W + i) * g + k];
    }
}

// ---------------- bf16 hi/lo coefficient repack (layers 2,3): -> [o][f]
__global__ void pack_bf16(const float* __restrict__ src, int which,
                          int dout, int W, int total) {
    __nv_bfloat16* dh = (which == 0) ? g_B2h : g_B3h;
    __nv_bfloat16* dl = (which == 0) ? g_B2l : g_B3l;
    const int g = 5, nw = 7;
    int KT = nw * W * 10;
    for (int idx = blockIdx.x * blockDim.x + threadIdx.x; idx < total;
         idx += gridDim.x * blockDim.x) {
        int o = idx / KT;
        int f = idx - o * KT;
        int trig = f & 1;
        int f2 = f >> 1;
        int k = f2 % g;
        int wi = f2 / g;
        int w = wi / W;
        int i = wi - w * W;
        float v = src[((((size_t)trig * dout + o) * nw + w) * W + i) * g + k];
        __nv_bfloat16 h = __float2bfloat16(v);
        __nv_bfloat16 l = __float2bfloat16(v - __bfloat162float(h));
        dh[idx] = h;
        dl[idx] = l;
    }
}

// ---------------- kNN: register top-20 per query thread ----------------
__global__ void knn_kernel(const float* __restrict__ pos) {
    __shared__ float sx[PPC], sy[PPC], sz[PPC];
    int tid = threadIdx.x;
    int b   = blockIdx.x >> 2;
    int ql  = ((blockIdx.x & 3) << 8) + tid;
    for (int p = tid; p < PPC; p += 256) {
        const float* pp = pos + (b * PPC + p) * 3;
        sx[p] = pp[0]; sy[p] = pp[1]; sz[p] = pp[2];
    }
    __syncthreads();
    float qx = sx[ql], qy = sy[ql], qz = sz[ql];
    float v[KNN]; int id[KNN];
#pragma unroll
    for (int j = 0; j < KNN; ++j) { v[j] = 1e30f; id[j] = -1; }
    float vmax = 1e30f; int mpos = 0;
    for (int p = 0; p < PPC; ++p) {
        float dx = sx[p] - qx, dy = sy[p] - qy, dz = sz[p] - qz;
        float d = dx * dx + dy * dy + dz * dz;
        if (p == ql) d = 1e30f;
        if (d < vmax) {
#pragma unroll
            for (int j = 0; j < KNN; ++j) if (j == mpos) { v[j] = d; id[j] = p; }
            vmax = v[0]; mpos = 0;
#pragma unroll
            for (int j = 1; j < KNN; ++j) if (v[j] > vmax) { vmax = v[j]; mpos = j; }
        }
    }
    int q = b * PPC + ql;
#pragma unroll
    for (int j = 0; j < KNN; ++j) g_nbr[q * KNN + j] = b * PPC + id[j];
}

// ---------------- layer1: edge feats -> 64 channels, transposed output ------
__global__ void layer1_kernel(const float* __restrict__ pos,
                              const float* __restrict__ b1) {
    __shared__ float Cs[60 * 64];
    __shared__ float bs[64];
    __shared__ float tr[64 * 129];
    int tid = threadIdx.x;                   // 128
    for (int i = tid; i < 60 * 64; i += 128) Cs[i] = g_Bp1[i];
    if (tid < 64) bs[tid] = b1[tid];
    __syncthreads();
    int edge = blockIdx.x * 128 + tid;
    int n = edge / KNN;
    int pj = g_nbr[edge];
    const float* Pi = pos + n * 3;
    const float* Pj = pos + pj * 3;
    float e[6];
    e[0] = Pi[0]; e[1] = Pi[1]; e[2] = Pi[2];
    e[3] = Pj[0] - Pi[0]; e[4] = Pj[1] - Pi[1]; e[5] = Pj[2] - Pi[2];
    float acc[64];
#pragma unroll
    for (int o = 0; o < 64; ++o) acc[o] = bs[o];
#pragma unroll
    for (int d = 0; d < 6; ++d) {
        int i = d % 3;
        float ham = 0.54f - 0.46f * cosf(6.2831853071795864f * (float)i / 2.0f);
        float a = e[d] * ham;
        float s, c; __sincosf(a, &s, &c);
        float ck = c, sk = s;
#pragma unroll
        for (int k = 0; k < 5; ++k) {
            if (k > 0) { float cn = ck * c - sk * s, sn = sk * c + ck * s; ck = cn; sk = sn; }
            int f = (d * 5 + k) * 2;
            const float4* c4 = (const float4*)&Cs[f * 64];
            const float4* s4 = (const float4*)&Cs[(f + 1) * 64];
#pragma unroll
            for (int o4 = 0; o4 < 16; ++o4) {
                float4 cc = c4[o4], ss = s4[o4];
                acc[o4 * 4 + 0] += ck * cc.x + sk * ss.x;
                acc[o4 * 4 + 1] += ck * cc.y + sk * ss.y;
                acc[o4 * 4 + 2] += ck * cc.z + sk * ss.z;
                acc[o4 * 4 + 3] += ck * cc.w + sk * ss.w;
            }
        }
    }
    // transpose via shared, write coalesced columns
#pragma unroll
    for (int o = 0; o < 64; ++o) tr[o * 129 + tid] = acc[o];
    __syncthreads();
    int e0 = blockIdx.x * 128;
#pragma unroll
    for (int o = 0; o < 64; ++o)
        g_h1T[o * NEDGE + e0 + tid] = tr[o * 129 + tid];
}

// ---------------- bf16x3 tensor-core fused-basis GEMM (layers 2,3) ----------
__device__ __forceinline__ void mma_bf16(float* c, uint32_t a0, uint32_t a1,
                                         uint32_t a2, uint32_t a3,
                                         uint32_t b0, uint32_t b1) {
    asm volatile(
        "mma.sync.aligned.m16n8k16.row.col.f32.bf16.bf16.f32 "
        "{%0,%1,%2,%3}, {%4,%5,%6,%7}, {%8,%9}, {%0,%1,%2,%3};\n"
        : "+f"(c[0]), "+f"(c[1]), "+f"(c[2]), "+f"(c[3])
        : "r"(a0), "r"(a1), "r"(a2), "r"(a3), "r"(b0), "r"(b1));
}

__device__ __forceinline__ uint32_t pack2(__nv_bfloat16 lo16, __nv_bfloat16 hi16) {
    return ((uint32_t)__bfloat16_as_ushort(hi16) << 16) |
           (uint32_t)__bfloat16_as_ushort(lo16);
}

template<int LAYER>
__global__ void __launch_bounds__(256, 2)
kan_mma(const float* __restrict__ bias) {
    constexpr int W    = (LAYER == 2) ? 16 : 32;
    constexpr int S    = (LAYER == 2) ? 8  : 16;
    constexpr int DOUT = (LAYER == 2) ? 128 : 1024;
    constexpr int M    = (LAYER == 2) ? NEDGE : NPTS;
    constexpr int COLS = 7 * W;          // 112 / 224
    constexpr int NCH  = COLS / 8;       // 14 / 28
    constexpr int KTOT = COLS * 10;      // 1120 / 2240
    constexpr int SA   = 88;             // padded k-stride (bf16 units)

    extern __shared__ unsigned char dynsm[];
    __nv_bfloat16* sAh = (__nv_bfloat16*)dynsm;
    __nv_bfloat16* sAl = sAh + 128 * SA;
    __nv_bfloat16* sBh = sAl + 128 * SA;
    __nv_bfloat16* sBl = sBh + 128 * SA;

    const float* x = (LAYER == 2) ? g_h1T : g_x1T;     // [d][M]
    const __nv_bfloat16* Bh = (LAYER == 2) ? g_B2h : g_B3h;
    const __nv_bfloat16* Bl = (LAYER == 2) ? g_B2l : g_B3l;
    float* y = (LAYER == 2) ? g_y2 : g_x3;

    int m0 = blockIdx.x * 128;
    int n0 = blockIdx.y * 128;
    int tid = threadIdx.x;
    int lane = tid & 31, warp = tid >> 5;
    int wm = warp & 3, wn = warp >> 2;   // warp tile: 32 rows x 64 cols
    int qr = lane >> 2, qk = lane & 3;

    float acc[2][8][4];
#pragma unroll
    for (int m = 0; m < 2; ++m)
#pragma unroll
        for (int n = 0; n < 8; ++n)
#pragma unroll
            for (int q = 0; q < 4; ++q) acc[m][n][q] = 0.f;

    for (int ch = 0; ch < NCH; ++ch) {
        __syncthreads();
        if (tid < 128) {
            // basis generation for 8 window-positions (80 features)
            int row = tid;
#pragma unroll
            for (int cc = 0; cc < 8; ++cc) {
                int col = ch * 8 + cc;
                int w = col / W, i = col - w * W;
                int d = w * S + i;
                float ham = 0.54f - 0.46f * cosf(6.2831853071795864f * (float)i / (float)(W - 1));
                float a = x[(size_t)d * M + m0 + row] * ham;
                float s, c; __sincosf(a, &s, &c);
                float ck = c, sk = s;
                uint32_t* ph = (uint32_t*)&sAh[row * SA + cc * 10];
                uint32_t* pl = (uint32_t*)&sAl[row * SA + cc * 10];
#pragma unroll
                for (int k = 0; k < 5; ++k) {
                    if (k > 0) { float cn = ck * c - sk * s, sn = sk * c + ck * s; ck = cn; sk = sn; }
                    __nv_bfloat16 chh = __float2bfloat16(ck);
                    __nv_bfloat16 shh = __float2bfloat16(sk);
                    __nv_bfloat16 cll = __float2bfloat16(ck - __bfloat162float(chh));
                    __nv_bfloat16 sll = __float2bfloat16(sk - __bfloat162float(shh));
                    ph[k] = pack2(chh, shh);   // (cos, sin) adjacent features
                    pl[k] = pack2(cll, sll);
                }
            }
        } else {
            // stage B tile: 128 rows x 80 k (bf16), hi + lo
            int r = tid - 128;
            const uint4* gh = (const uint4*)(Bh + (size_t)(n0 + r) * KTOT + ch * 80);
            const uint4* gl = (const uint4*)(Bl + (size_t)(n0 + r) * KTOT + ch * 80);
            uint4* shp = (uint4*)(sBh + r * SA);
            uint4* slp = (uint4*)(sBl + r * SA);
#pragma unroll
            for (int q = 0; q < 10; ++q) shp[q] = gh[q];
#pragma unroll
            for (int q = 0; q < 10; ++q) slp[q] = gl[q];
        }
        __syncthreads();

#pragma unroll
        for (int ks = 0; ks < 5; ++ks) {
            int kb = ks * 16;
            uint32_t ah[2][4], al[2][4];
#pragma unroll
            for (int m = 0; m < 2; ++m) {
                int rb = (wm * 32 + m * 16 + qr) * SA + kb + qk * 2;
                ah[m][0] = *(const uint32_t*)&sAh[rb];
                ah[m][1] = *(const uint32_t*)&sAh[rb + 8 * SA];
                ah[m][2] = *(const uint32_t*)&sAh[rb + 8];
                ah[m][3] = *(const uint32_t*)&sAh[rb + 8 * SA + 8];
                al[m][0] = *(const uint32_t*)&sAl[rb];
                al[m][1] = *(const uint32_t*)&sAl[rb + 8 * SA];
                al[m][2] = *(const uint32_t*)&sAl[rb + 8];
                al[m][3] = *(const uint32_t*)&sAl[rb + 8 * SA + 8];
            }
#pragma unroll
            for (int n = 0; n < 8; ++n) {
                int bb = (wn * 64 + n * 8 + qr) * SA + kb + qk * 2;
                uint32_t bh0 = *(const uint32_t*)&sBh[bb];
                uint32_t bh1 = *(const uint32_t*)&sBh[bb + 8];
                uint32_t bl0 = *(const uint32_t*)&sBl[bb];
                uint32_t bl1 = *(const uint32_t*)&sBl[bb + 8];
#pragma unroll
                for (int m = 0; m < 2; ++m) {
                    mma_bf16(acc[m][n], ah[m][0], ah[m][1], ah[m][2], ah[m][3], bh0, bh1);
                    mma_bf16(acc[m][n], al[m][0], al[m][1], al[m][2], al[m][3], bh0, bh1);
                    mma_bf16(acc[m][n], ah[m][0], ah[m][1], ah[m][2], ah[m][3], bl0, bl1);
                }
            }
        }
    }

    // epilogue
#pragma unroll
    for (int m = 0; m < 2; ++m) {
        int r0 = m0 + wm * 32 + m * 16 + qr;
#pragma unroll
        for (int n = 0; n < 8; ++n) {
            int c0 = n0 + wn * 64 + n * 8 + qk * 2;
            float bv0 = bias[c0], bv1 = bias[c0 + 1];
            float2 v0 = make_float2(acc[m][n][0] + bv0, acc[m][n][1] + bv1);
            float2 v1 = make_float2(acc[m][n][2] + bv0, acc[m][n][3] + bv1);
            *(float2*)&y[(size_t)r0 * DOUT + c0] = v0;
            *(float2*)&y[(size_t)(r0 + 8) * DOUT + c0] = v1;
        }
    }
}

// ---------------- max over K neighbors, transposed output -------------------
__global__ void maxagg_kernel() {
    extern __shared__ unsigned char dynsm[];
    float* s = (float*)dynsm;               // [128][133]
    int n0 = blockIdx.x * 128;
    for (int idx = threadIdx.x; idx < 128 * 128; idx += 256) {
        int p = idx >> 7, c = idx & 127;
        const float* src = g_y2 + ((size_t)(n0 + p) * KNN) * 128 + c;
        float m = src[0];
#pragma unroll
        for (int j = 1; j < KNN; ++j) m = fmaxf(m, src[j * 128]);
        s[c * 133 + p] = m;
    }
    __syncthreads();
    for (int idx = threadIdx.x; idx < 128 * 128; idx += 256) {
        int c = idx >> 7, p = idx & 127;
        g_x1T[(size_t)c * NPTS + n0 + p] = s[c * 133 + p];
    }
}

// ---------------- segment max + mean pooling ----------------
__global__ void pool_kernel() {
    int b = blockIdx.x;
    int c = blockIdx.y * 128 + threadIdx.x;
    const float* p = g_x3 + (size_t)b * PPC * 1024 + c;
    float mx = -1e30f, sm = 0.f;
    for (int pt = 0; pt < PPC; ++pt) {
        float v = p[(size_t)pt * 1024];
        mx = fmaxf(mx, v); sm += v;
    }
    g_xg[b * 2048 + c] = mx;
    g_xg[b * 2048 + 1024 + c] = sm * (1.0f / 1024.0f);
}

// ---------------- layer4 ----------------
__global__ void layer4_part() {
    __shared__ float xs[2048];
    __shared__ float wsum[8][40];
    int b = blockIdx.x, sl = blockIdx.y, tid = threadIdx.x;
    for (int i = tid; i < 2048; i += 256) xs[i] = g_xg[b * 2048 + i];
    __syncthreads();
    float acc[40];
#pragma unroll
    for (int o = 0; o < 40; ++o) acc[o] = 0.f;
    for (int pp = tid; pp < 480; pp += 256) {
        int p = sl * 480 + pp;
        int w = p >> 8, i = p & 255;
        int d = (w << 7) + i;
        float ham = 0.54f - 0.46f * cosf(6.2831853071795864f * (float)i / 255.0f);
        float a = xs[d] * ham;
        float s, c; __sincosf(a, &s, &c);
        float ck = c, sk = s;
        const float* bp = g_Bp4 + p * 400;
#pragma unroll
        for (int k = 0; k < 5; ++k) {
            if (k > 0) { float cn = ck * c - sk * s, sn = sk * c + ck * s; ck = cn; sk = sn; }
            const float* c0 = bp + (2 * k) * 40;
            const float* s0 = bp + (2 * k + 1) * 40;
#pragma unroll
            for (int o = 0; o < 40; ++o) acc[o] += ck * c0[o] + sk * s0[o];
        }
    }
    int lane = tid & 31, wp = tid >> 5;
#pragma unroll
    for (int o = 0; o < 40; ++o) {
        float t = acc[o];
#pragma unroll
        for (int off = 16; off > 0; off >>= 1) t += __shfl_down_sync(0xffffffffu, t, off);
        if (lane == 0) wsum[wp][o] = t;
    }
    __syncthreads();
    if (tid < 40) {
        float t = 0.f;
#pragma unroll
        for (int w8 = 0; w8 < 8; ++w8) t += wsum[w8][tid];
        g_l4p[(b * 8 + sl) * 40 + tid] = t;
    }
}

__global__ void layer4_final(const float* __restrict__ b4, float* __restrict__ out) {
    int t = threadIdx.x;
    if (t < 320) {
        int o = t % 40;
        int b = t / 40;
        float s = b4[o];
#pragma unroll
        for (int sl = 0; sl < 8; ++sl) s += g_l4p[(b * 8 + sl) * 40 + o];
        out[t] = s;
    }
}

// ---------------- launch ----------------
extern "C" void kernel_launch(void* const* d_in, const int* in_sizes, int n_in,
                              void* d_out, int out_size) {
    (void)in_sizes; (void)n_in; (void)out_size;
    const float* pos = (const float*)d_in[0];
    const float* c1  = (const float*)d_in[2];
    const float* b1  = (const float*)d_in[3];
    const float* c2  = (const float*)d_in[4];
    const float* b2  = (const float*)d_in[5];
    const float* c3  = (const float*)d_in[6];
    const float* b3  = (const float*)d_in[7];
    const float* c4  = (const float*)d_in[8];
    const float* b4  = (const float*)d_in[9];
    float* out = (float*)d_out;

    const int SM_MMA = 4 * 128 * 88 * 2;        // 90112 B
    const int SM_MAX = 128 * 133 * 4;           // 68096 B
    cudaFuncSetAttribute(kan_mma<2>, cudaFuncAttributeMaxDynamicSharedMemorySize, SM_MMA);
    cudaFuncSetAttribute(kan_mma<3>, cudaFuncAttributeMaxDynamicSharedMemorySize, SM_MMA);
    cudaFuncSetAttribute(maxagg_kernel, cudaFuncAttributeMaxDynamicSharedMemorySize, SM_MAX);

    pack_coef<<<15, 256>>>(c1, 0, 64, 2, 3, 60 * 64);          // launch 0
    knn_kernel<<<32, 256>>>(pos);                              // 1
    layer1_kernel<<<NEDGE / 128, 128>>>(pos, b1);              // 2
    pack_bf16<<<560, 256>>>(c2, 0, 128, 16, 128 * 1120);       // 3
    pack_bf16<<<4096, 256>>>(c3, 1, 1024, 32, 1024 * 2240);    // 4
    kan_mma<2><<<dim3(NEDGE / 128, 1), 256, SM_MMA>>>(b2);     // 5  <- ncu capture
    maxagg_kernel<<<NPTS / 128, 256, SM_MAX>>>();
    kan_mma<3><<<dim3(NPTS / 128, 8), 256, SM_MMA>>>(b3);
    pack_coef<<<6000, 256>>>(c4, 3, 40, 15, 256, 38400 * 40);
    pool_kernel<<<dim3(NB, 8), 128>>>();
    layer4_part<<<dim3(NB, 8), 256>>>();
    layer4_final<<<1, 320>>>(b4, out);
}

// round 7
// speedup vs baseline: 1.5708x; 1.0146x over previous
#include <cuda_runtime.h>
#include <cuda_bf16.h>
#include <cstdint>

#define NB    8
#define PPC   1024
#define NPTS  8192
#define KNN   20
#define NEDGE (NPTS*KNN)

// ---------------- scratch (device globals; allocation-free) ----------------
__device__ int   g_nbr[NEDGE];
__device__ __align__(16) float g_h1T[64*NEDGE];    // layer1 out, TRANSPOSED [c][edge]
__device__ __align__(16) float g_y2[NEDGE*128];    // layer2 out (pre-max), row-major
__device__ __align__(16) float g_x1T[128*NPTS];    // after max over K, TRANSPOSED [c][n]
__device__ __align__(16) float g_x3[NPTS*1024];    // layer3 out, row-major
__device__ float g_xg[NB*2048];                    // pooled [max | mean]
__device__ __align__(16) float g_Bp1[60*64];       // layer1 coeffs [f][o]
__device__ __align__(16) float g_Bp4[38400*40];    // layer4 coeffs [f][o]
__device__ __align__(16) __nv_bfloat16 g_B2h[128*1120];   // layer2 coeffs [o][f] hi
__device__ __align__(16) __nv_bfloat16 g_B2l[128*1120];   // lo
__device__ __align__(16) __nv_bfloat16 g_B3h[1024*2240];  // layer3 [o][f] hi
__device__ __align__(16) __nv_bfloat16 g_B3l[1024*2240];  // lo
__device__ float g_l4p[NB*8*40];

// ---------------- fp32 coefficient repack (layers 1,4): (2,dout,nw,W,g) -> [f][o]
// f = ((w*W+i)*g + k)*2 + trig
__global__ void pack_coef(const float* __restrict__ src, int which,
                          int dout, int nw, int W, int total) {
    float* dst = (which == 0) ? g_Bp1 : g_Bp4;
    const int g = 5;
    for (int idx = blockIdx.x * blockDim.x + threadIdx.x; idx < total;
         idx += gridDim.x * blockDim.x) {
        int o = idx % dout;
        int f = idx / dout;
        int trig = f & 1;
        int f2 = f >> 1;
        int k = f2 % g;
        int wi = f2 / g;
        int w = wi / W;
        int i = wi - w * W;
        dst[idx] = src[((((trig * dout) + o) * nw + w) * W + i) * g + k];
    }
}

// ---------------- bf16 hi/lo coefficient repack (layers 2,3): -> [o][f]
__global__ void pack_bf16(const float* __restrict__ src, int which,
                          int dout, int W, int total) {
    __nv_bfloat16* dh = (which == 0) ? g_B2h : g_B3h;
    __nv_bfloat16* dl = (which == 0) ? g_B2l : g_B3l;
    const int g = 5, nw = 7;
    int KT = nw * W * 10;
    for (int idx = blockIdx.x * blockDim.x + threadIdx.x; idx < total;
         idx += gridDim.x * blockDim.x) {
        int o = idx / KT;
        int f = idx - o * KT;
        int trig = f & 1;
        int f2 = f >> 1;
        int k = f2 % g;
        int wi = f2 / g;
        int w = wi / W;
        int i = wi - w * W;
        float v = src[((((size_t)trig * dout + o) * nw + w) * W + i) * g + k];
        __nv_bfloat16 h = __float2bfloat16(v);
        __nv_bfloat16 l = __float2bfloat16(v - __bfloat162float(h));
        dh[idx] = h;
        dl[idx] = l;
    }
}

// ---------------- kNN: register top-20 per query thread ----------------
__global__ void knn_kernel(const float* __restrict__ pos) {
    __shared__ float sx[PPC], sy[PPC], sz[PPC];
    int tid = threadIdx.x;
    int b   = blockIdx.x >> 2;
    int ql  = ((blockIdx.x & 3) << 8) + tid;
    for (int p = tid; p < PPC; p += 256) {
        const float* pp = pos + (b * PPC + p) * 3;
        sx[p] = pp[0]; sy[p] = pp[1]; sz[p] = pp[2];
    }
    __syncthreads();
    float qx = sx[ql], qy = sy[ql], qz = sz[ql];
    float v[KNN]; int id[KNN];
#pragma unroll
    for (int j = 0; j < KNN; ++j) { v[j] = 1e30f; id[j] = -1; }
    float vmax = 1e30f; int mpos = 0;
    for (int p = 0; p < PPC; ++p) {
        float dx = sx[p] - qx, dy = sy[p] - qy, dz = sz[p] - qz;
        float d = dx * dx + dy * dy + dz * dz;
        if (p == ql) d = 1e30f;
        if (d < vmax) {
#pragma unroll
            for (int j = 0; j < KNN; ++j) if (j == mpos) { v[j] = d; id[j] = p; }
            vmax = v[0]; mpos = 0;
#pragma unroll
            for (int j = 1; j < KNN; ++j) if (v[j] > vmax) { vmax = v[j]; mpos = j; }
        }
    }
    int q = b * PPC + ql;
#pragma unroll
    for (int j = 0; j < KNN; ++j) g_nbr[q * KNN + j] = b * PPC + id[j];
}

// ---------------- layer1: edge feats -> 64 channels, transposed output ------
__global__ void layer1_kernel(const float* __restrict__ pos,
                              const float* __restrict__ b1) {
    __shared__ float Cs[60 * 64];
    __shared__ float bs[64];
    __shared__ float tr[64 * 129];
    int tid = threadIdx.x;                   // 128
    for (int i = tid; i < 60 * 64; i += 128) Cs[i] = g_Bp1[i];
    if (tid < 64) bs[tid] = b1[tid];
    __syncthreads();
    int edge = blockIdx.x * 128 + tid;
    int n = edge / KNN;
    int pj = g_nbr[edge];
    const float* Pi = pos + n * 3;
    const float* Pj = pos + pj * 3;
    float e[6];
    e[0] = Pi[0]; e[1] = Pi[1]; e[2] = Pi[2];
    e[3] = Pj[0] - Pi[0]; e[4] = Pj[1] - Pi[1]; e[5] = Pj[2] - Pi[2];
    float acc[64];
#pragma unroll
    for (int o = 0; o < 64; ++o) acc[o] = bs[o];
#pragma unroll
    for (int d = 0; d < 6; ++d) {
        int i = d % 3;
        float ham = 0.54f - 0.46f * cosf(6.2831853071795864f * (float)i / 2.0f);
        float a = e[d] * ham;
        float s, c; __sincosf(a, &s, &c);
        float ck = c, sk = s;
#pragma unroll
        for (int k = 0; k < 5; ++k) {
            if (k > 0) { float cn = ck * c - sk * s, sn = sk * c + ck * s; ck = cn; sk = sn; }
            int f = (d * 5 + k) * 2;
            const float4* c4 = (const float4*)&Cs[f * 64];
            const float4* s4 = (const float4*)&Cs[(f + 1) * 64];
#pragma unroll
            for (int o4 = 0; o4 < 16; ++o4) {
                float4 cc = c4[o4], ss = s4[o4];
                acc[o4 * 4 + 0] += ck * cc.x + sk * ss.x;
                acc[o4 * 4 + 1] += ck * cc.y + sk * ss.y;
                acc[o4 * 4 + 2] += ck * cc.z + sk * ss.z;
                acc[o4 * 4 + 3] += ck * cc.w + sk * ss.w;
            }
        }
    }
    // transpose via shared, write coalesced columns
#pragma unroll
    for (int o = 0; o < 64; ++o) tr[o * 129 + tid] = acc[o];
    __syncthreads();
    int e0 = blockIdx.x * 128;
#pragma unroll
    for (int o = 0; o < 64; ++o)
        g_h1T[o * NEDGE + e0 + tid] = tr[o * 129 + tid];
}

// ---------------- bf16x3 tensor-core fused-basis GEMM (layers 2,3) ----------
__device__ __forceinline__ void mma_bf16(float* c, uint32_t a0, uint32_t a1,
                                         uint32_t a2, uint32_t a3,
                                         uint32_t b0, uint32_t b1) {
    asm volatile(
        "mma.sync.aligned.m16n8k16.row.col.f32.bf16.bf16.f32 "
        "{%0,%1,%2,%3}, {%4,%5,%6,%7}, {%8,%9}, {%0,%1,%2,%3};\n"
        : "+f"(c[0]), "+f"(c[1]), "+f"(c[2]), "+f"(c[3])
        : "r"(a0), "r"(a1), "r"(a2), "r"(a3), "r"(b0), "r"(b1));
}

__device__ __forceinline__ uint32_t pack2(__nv_bfloat16 lo16, __nv_bfloat16 hi16) {
    return ((uint32_t)__bfloat16_as_ushort(hi16) << 16) |
           (uint32_t)__bfloat16_as_ushort(lo16);
}

template<int LAYER>
__global__ void __launch_bounds__(256, 2)
kan_mma(const float* __restrict__ bias) {
    constexpr int W    = (LAYER == 2) ? 16 : 32;
    constexpr int S    = (LAYER == 2) ? 8  : 16;
    constexpr int DOUT = (LAYER == 2) ? 128 : 1024;
    constexpr int M    = (LAYER == 2) ? NEDGE : NPTS;
    constexpr int COLS = 7 * W;          // 112 / 224
    constexpr int NCH  = COLS / 8;       // 14 / 28
    constexpr int KTOT = COLS * 10;      // 1120 / 2240
    constexpr int SA   = 88;             // padded k-stride (bf16 units)

    extern __shared__ unsigned char dynsm[];
    __nv_bfloat16* sAh = (__nv_bfloat16*)dynsm;
    __nv_bfloat16* sAl = sAh + 128 * SA;
    __nv_bfloat16* sBh = sAl + 128 * SA;
    __nv_bfloat16* sBl = sBh + 128 * SA;

    const float* x = (LAYER == 2) ? g_h1T : g_x1T;     // [d][M]
    const __nv_bfloat16* Bh = (LAYER == 2) ? g_B2h : g_B3h;
    const __nv_bfloat16* Bl = (LAYER == 2) ? g_B2l : g_B3l;
    float* y = (LAYER == 2) ? g_y2 : g_x3;

    int m0 = blockIdx.x * 128;
    int n0 = blockIdx.y * 128;
    int tid = threadIdx.x;
    int lane = tid & 31, warp = tid >> 5;
    int wm = warp & 3, wn = warp >> 2;   // warp tile: 32 rows x 64 cols
    int qr = lane >> 2, qk = lane & 3;

    float acc[2][8][4];
#pragma unroll
    for (int m = 0; m < 2; ++m)
#pragma unroll
        for (int n = 0; n < 8; ++n)
#pragma unroll
            for (int q = 0; q < 4; ++q) acc[m][n][q] = 0.f;

    for (int ch = 0; ch < NCH; ++ch) {
        __syncthreads();
        if (tid < 128) {
            // basis generation for 8 window-positions (80 features)
            int row = tid;
#pragma unroll
            for (int cc = 0; cc < 8; ++cc) {
                int col = ch * 8 + cc;
                int w = col / W, i = col - w * W;
                int d = w * S + i;
                float ham = 0.54f - 0.46f * cosf(6.2831853071795864f * (float)i / (float)(W - 1));
                float a = x[(size_t)d * M + m0 + row] * ham;
                float s, c; __sincosf(a, &s, &c);
                float ck = c, sk = s;
                uint32_t* ph = (uint32_t*)&sAh[row * SA + cc * 10];
                uint32_t* pl = (uint32_t*)&sAl[row * SA + cc * 10];
#pragma unroll
                for (int k = 0; k < 5; ++k) {
                    if (k > 0) { float cn = ck * c - sk * s, sn = sk * c + ck * s; ck = cn; sk = sn; }
                    __nv_bfloat16 chh = __float2bfloat16(ck);
                    __nv_bfloat16 shh = __float2bfloat16(sk);
                    __nv_bfloat16 cll = __float2bfloat16(ck - __bfloat162float(chh));
                    __nv_bfloat16 sll = __float2bfloat16(sk - __bfloat162float(shh));
                    ph[k] = pack2(chh, shh);   // (cos, sin) adjacent features
                    pl[k] = pack2(cll, sll);
                }
            }
        } else {
            // stage B tile: 128 rows x 80 k (bf16), hi + lo
            int r = tid - 128;
            const uint4* gh = (const uint4*)(Bh + (size_t)(n0 + r) * KTOT + ch * 80);
            const uint4* gl = (const uint4*)(Bl + (size_t)(n0 + r) * KTOT + ch * 80);
            uint4* shp = (uint4*)(sBh + r * SA);
            uint4* slp = (uint4*)(sBl + r * SA);
#pragma unroll
            for (int q = 0; q < 10; ++q) shp[q] = gh[q];
#pragma unroll
            for (int q = 0; q < 10; ++q) slp[q] = gl[q];
        }
        __syncthreads();

#pragma unroll
        for (int ks = 0; ks < 5; ++ks) {
            int kb = ks * 16;
            uint32_t ah[2][4], al[2][4];
#pragma unroll
            for (int m = 0; m < 2; ++m) {
                int rb = (wm * 32 + m * 16 + qr) * SA + kb + qk * 2;
                ah[m][0] = *(const uint32_t*)&sAh[rb];
                ah[m][1] = *(const uint32_t*)&sAh[rb + 8 * SA];
                ah[m][2] = *(const uint32_t*)&sAh[rb + 8];
                ah[m][3] = *(const uint32_t*)&sAh[rb + 8 * SA + 8];
                al[m][0] = *(const uint32_t*)&sAl[rb];
                al[m][1] = *(const uint32_t*)&sAl[rb + 8 * SA];
                al[m][2] = *(const uint32_t*)&sAl[rb + 8];
                al[m][3] = *(const uint32_t*)&sAl[rb + 8 * SA + 8];
            }
#pragma unroll
            for (int n = 0; n < 8; ++n) {
                int bb = (wn * 64 + n * 8 + qr) * SA + kb + qk * 2;
                uint32_t bh0 = *(const uint32_t*)&sBh[bb];
                uint32_t bh1 = *(const uint32_t*)&sBh[bb + 8];
                uint32_t bl0 = *(const uint32_t*)&sBl[bb];
                uint32_t bl1 = *(const uint32_t*)&sBl[bb + 8];
#pragma unroll
                for (int m = 0; m < 2; ++m) {
                    mma_bf16(acc[m][n], ah[m][0], ah[m][1], ah[m][2], ah[m][3], bh0, bh1);
                    mma_bf16(acc[m][n], al[m][0], al[m][1], al[m][2], al[m][3], bh0, bh1);
                    mma_bf16(acc[m][n], ah[m][0], ah[m][1], ah[m][2], ah[m][3], bl0, bl1);
                }
            }
        }
    }

    // epilogue
#pragma unroll
    for (int m = 0; m < 2; ++m) {
        int r0 = m0 + wm * 32 + m * 16 + qr;
#pragma unroll
        for (int n = 0; n < 8; ++n) {
            int c0 = n0 + wn * 64 + n * 8 + qk * 2;
            float bv0 = bias[c0], bv1 = bias[c0 + 1];
            float2 v0 = make_float2(acc[m][n][0] + bv0, acc[m][n][1] + bv1);
            float2 v1 = make_float2(acc[m][n][2] + bv0, acc[m][n][3] + bv1);
            *(float2*)&y[(size_t)r0 * DOUT + c0] = v0;
            *(float2*)&y[(size_t)(r0 + 8) * DOUT + c0] = v1;
        }
    }
}

// ---------------- max over K neighbors, transposed output -------------------
__global__ void maxagg_kernel() {
    extern __shared__ unsigned char dynsm[];
    float* s = (float*)dynsm;               // [128][133]
    int n0 = blockIdx.x * 128;
    for (int idx = threadIdx.x; idx < 128 * 128; idx += 256) {
        int p = idx >> 7, c = idx & 127;
        const float* src = g_y2 + ((size_t)(n0 + p) * KNN) * 128 + c;
        float m = src[0];
#pragma unroll
        for (int j = 1; j < KNN; ++j) m = fmaxf(m, src[j * 128]);
        s[c * 133 + p] = m;
    }
    __syncthreads();
    for (int idx = threadIdx.x; idx < 128 * 128; idx += 256) {
        int c = idx >> 7, p = idx & 127;
        g_x1T[(size_t)c * NPTS + n0 + p] = s[c * 133 + p];
    }
}

// ---------------- segment max + mean pooling ----------------
__global__ void pool_kernel() {
    int b = blockIdx.x;
    int c = blockIdx.y * 128 + threadIdx.x;
    const float* p = g_x3 + (size_t)b * PPC * 1024 + c;
    float mx = -1e30f, sm = 0.f;
    for (int pt = 0; pt < PPC; ++pt) {
        float v = p[(size_t)pt * 1024];
        mx = fmaxf(mx, v); sm += v;
    }
    g_xg[b * 2048 + c] = mx;
    g_xg[b * 2048 + 1024 + c] = sm * (1.0f / 1024.0f);
}

// ---------------- layer4 ----------------
__global__ void layer4_part() {
    __shared__ float xs[2048];
    __shared__ float wsum[8][40];
    int b = blockIdx.x, sl = blockIdx.y, tid = threadIdx.x;
    for (int i = tid; i < 2048; i += 256) xs[i] = g_xg[b * 2048 + i];
    __syncthreads();
    float acc[40];
#pragma unroll
    for (int o = 0; o < 40; ++o) acc[o] = 0.f;
    for (int pp = tid; pp < 480; pp += 256) {
        int p = sl * 480 + pp;
        int w = p >> 8, i = p & 255;
        int d = (w << 7) + i;
        float ham = 0.54f - 0.46f * cosf(6.2831853071795864f * (float)i / 255.0f);
        float a = xs[d] * ham;
        float s, c; __sincosf(a, &s, &c);
        float ck = c, sk = s;
        const float* bp = g_Bp4 + p * 400;
#pragma unroll
        for (int k = 0; k < 5; ++k) {
            if (k > 0) { float cn = ck * c - sk * s, sn = sk * c + ck * s; ck = cn; sk = sn; }
            const float* c0 = bp + (2 * k) * 40;
            const float* s0 = bp + (2 * k + 1) * 40;
#pragma unroll
            for (int o = 0; o < 40; ++o) acc[o] += ck * c0[o] + sk * s0[o];
        }
    }
    int lane = tid & 31, wp = tid >> 5;
#pragma unroll
    for (int o = 0; o < 40; ++o) {
        float t = acc[o];
#pragma unroll
        for (int off = 16; off > 0; off >>= 1) t += __shfl_down_sync(0xffffffffu, t, off);
        if (lane == 0) wsum[wp][o] = t;
    }
    __syncthreads();
    if (tid < 40) {
        float t = 0.f;
#pragma unroll
        for (int w8 = 0; w8 < 8; ++w8) t += wsum[w8][tid];
        g_l4p[(b * 8 + sl) * 40 + tid] = t;
    }
}

__global__ void layer4_final(const float* __restrict__ b4, float* __restrict__ out) {
    int t = threadIdx.x;
    if (t < 320) {
        int o = t % 40;
        int b = t / 40;
        float s = b4[o];
#pragma unroll
        for (int sl = 0; sl < 8; ++sl) s += g_l4p[(b * 8 + sl) * 40 + o];
        out[t] = s;
    }
}

// ---------------- launch ----------------
extern "C" void kernel_launch(void* const* d_in, const int* in_sizes, int n_in,
                              void* d_out, int out_size) {
    (void)in_sizes; (void)n_in; (void)out_size;
    const float* pos = (const float*)d_in[0];
    const float* c1  = (const float*)d_in[2];
    const float* b1  = (const float*)d_in[3];
    const float* c2  = (const float*)d_in[4];
    const float* b2  = (const float*)d_in[5];
    const float* c3  = (const float*)d_in[6];
    const float* b3  = (const float*)d_in[7];
    const float* c4  = (const float*)d_in[8];
    const float* b4  = (const float*)d_in[9];
    float* out = (float*)d_out;

    const int SM_MMA = 4 * 128 * 88 * 2;        // 90112 B
    const int SM_MAX = 128 * 133 * 4;           // 68096 B
    cudaFuncSetAttribute(kan_mma<2>, cudaFuncAttributeMaxDynamicSharedMemorySize, SM_MMA);
    cudaFuncSetAttribute(kan_mma<3>, cudaFuncAttributeMaxDynamicSharedMemorySize, SM_MMA);
    cudaFuncSetAttribute(maxagg_kernel, cudaFuncAttributeMaxDynamicSharedMemorySize, SM_MAX);

    pack_coef<<<15, 256>>>(c1, 0, 64, 2, 3, 60 * 64);          // launch 0
    knn_kernel<<<32, 256>>>(pos);                              // 1
    layer1_kernel<<<NEDGE / 128, 128>>>(pos, b1);              // 2
    pack_bf16<<<560, 256>>>(c2, 0, 128, 16, 128 * 1120);       // 3
    pack_bf16<<<4096, 256>>>(c3, 1, 1024, 32, 1024 * 2240);    // 4
    kan_mma<2><<<dim3(NEDGE / 128, 1), 256, SM_MMA>>>(b2);     // 5  <- ncu capture
    maxagg_kernel<<<NPTS / 128, 256, SM_MAX>>>();
    kan_mma<3><<<dim3(NPTS / 128, 8), 256, SM_MMA>>>(b3);
    pack_coef<<<6000, 256>>>(c4, 3, 40, 15, 256, 38400 * 40);
    pool_kernel<<<dim3(NB, 8), 128>>>();
    layer4_part<<<dim3(NB, 8), 256>>>();
    layer4_final<<<1, 320>>>(b4, out);
}

// round 9
// speedup vs baseline: 2.1306x; 1.3564x over previous
#include <cuda_runtime.h>
#include <cuda_fp16.h>
#include <cstdint>

#define NB    8
#define PPC   1024
#define NPTS  8192
#define KNN   20
#define NEDGE (NPTS*KNN)

// ---------------- scratch (device globals; allocation-free) ----------------
__device__ int   g_nbr[NEDGE];
__device__ __align__(16) float g_h1T[64*NEDGE];    // layer1 out, TRANSPOSED [c][edge]
__device__ __align__(16) float g_y2[NEDGE*128];    // layer2 out (pre-max), row-major
__device__ __align__(16) float g_x1T[128*NPTS];    // after max over K, TRANSPOSED [c][n]
__device__ __align__(16) float g_x3[NPTS*1024];    // layer3 out, row-major
__device__ float g_xg[NB*2048];                    // pooled [max | mean]
__device__ __align__(16) float g_Bp4[38400*40];    // layer4 coeffs [f][o]
__device__ __align__(16) __half g_B2[128*1120];    // layer2 coeffs [o][f] fp16
__device__ __align__(16) __half g_B3[1024*2240];   // layer3 coeffs [o][f] fp16
__device__ float g_l4p[NB*8*40];

// ---------------- fp16 coefficient repack (layers 2,3): -> [o][f] -----------
// f = ((w*W+i)*g + k)*2 + trig
__global__ void pack_fp16(const float* __restrict__ src, int which,
                          int dout, int W, int total) {
    __half* dst = which ? g_B3 : g_B2;
    const int g = 5, nw = 7;
    int KT = nw * W * 10;
    for (int idx = blockIdx.x * blockDim.x + threadIdx.x; idx < total;
         idx += gridDim.x * blockDim.x) {
        int o = idx / KT;
        int f = idx - o * KT;
        int trig = f & 1;
        int f2 = f >> 1;
        int k = f2 % g;
        int wi = f2 / g;
        int w = wi / W;
        int i = wi - w * W;
        float v = src[((((size_t)trig * dout + o) * nw + w) * W + i) * g + k];
        dst[idx] = __float2half_rn(v);
    }
}

// ---------------- layer4 coeff repack ----------------
__global__ void pack_coef4(const float* __restrict__ src) {
    const int dout = 40, nw = 15, W = 256, g = 5;
    int idx = blockIdx.x * 256 + threadIdx.x;
    if (idx >= 38400 * 40) return;
    int o = idx % dout;
    int f = idx / dout;
    int trig = f & 1;
    int f2 = f >> 1;
    int k = f2 % g;
    int wi = f2 / g;
    int w = wi / W;
    int i = wi - w * W;
    g_Bp4[idx] = src[((((size_t)trig * dout + o) * nw + w) * W + i) * g + k];
}

// ---------------- kNN: register top-20 per query thread ----------------
__global__ void knn_kernel(const float* __restrict__ pos) {
    __shared__ float sx[PPC], sy[PPC], sz[PPC];
    int tid = threadIdx.x;
    int b   = blockIdx.x >> 2;
    int ql  = ((blockIdx.x & 3) << 8) + tid;
    for (int p = tid; p < PPC; p += 256) {
        const float* pp = pos + (b * PPC + p) * 3;
        sx[p] = pp[0]; sy[p] = pp[1]; sz[p] = pp[2];
    }
    __syncthreads();
    float qx = sx[ql], qy = sy[ql], qz = sz[ql];
    float v[KNN]; int id[KNN];
#pragma unroll
    for (int j = 0; j < KNN; ++j) { v[j] = 1e30f; id[j] = -1; }
    float vmax = 1e30f; int mpos = 0;
    for (int p = 0; p < PPC; ++p) {
        float dx = sx[p] - qx, dy = sy[p] - qy, dz = sz[p] - qz;
        float d = dx * dx + dy * dy + dz * dz;
        if (p == ql) d = 1e30f;
        if (d < vmax) {
#pragma unroll
            for (int j = 0; j < KNN; ++j) if (j == mpos) { v[j] = d; id[j] = p; }
            vmax = v[0]; mpos = 0;
#pragma unroll
            for (int j = 1; j < KNN; ++j) if (v[j] > vmax) { vmax = v[j]; mpos = j; }
        }
    }
    int q = b * PPC + ql;
#pragma unroll
    for (int j = 0; j < KNN; ++j) g_nbr[q * KNN + j] = b * PPC + id[j];
}

// ---------------- layer1 (reads raw c1, remap at smem load) -----------------
__global__ void layer1_kernel(const float* __restrict__ pos,
                              const float* __restrict__ c1,
                              const float* __restrict__ b1) {
    __shared__ float Cs[60 * 64];
    __shared__ float bs[64];
    __shared__ float tr[64 * 129];
    int tid = threadIdx.x;                   // 128
    for (int idx = tid; idx < 60 * 64; idx += 128) {
        int o = idx & 63, f = idx >> 6;
        int trig = f & 1, f2 = f >> 1, k = f2 % 5, wi = f2 / 5, w = wi / 3, i = wi - w * 3;
        Cs[idx] = c1[(((trig * 64 + o) * 2 + w) * 3 + i) * 5 + k];
    }
    if (tid < 64) bs[tid] = b1[tid];
    __syncthreads();
    int edge = blockIdx.x * 128 + tid;
    int n = edge / KNN;
    int pj = g_nbr[edge];
    const float* Pi = pos + n * 3;
    const float* Pj = pos + pj * 3;
    float e[6];
    e[0] = Pi[0]; e[1] = Pi[1]; e[2] = Pi[2];
    e[3] = Pj[0] - Pi[0]; e[4] = Pj[1] - Pi[1]; e[5] = Pj[2] - Pi[2];
    float acc[64];
#pragma unroll
    for (int o = 0; o < 64; ++o) acc[o] = bs[o];
#pragma unroll
    for (int d = 0; d < 6; ++d) {
        int i = d % 3;
        float ham = 0.54f - 0.46f * cosf(6.2831853071795864f * (float)i / 2.0f);
        float a = e[d] * ham;
        float s, c; __sincosf(a, &s, &c);
        float ck = c, sk = s;
#pragma unroll
        for (int k = 0; k < 5; ++k) {
            if (k > 0) { float cn = ck * c - sk * s, sn = sk * c + ck * s; ck = cn; sk = sn; }
            int f = (d * 5 + k) * 2;
            const float4* c4 = (const float4*)&Cs[f * 64];
            const float4* s4 = (const float4*)&Cs[(f + 1) * 64];
#pragma unroll
            for (int o4 = 0; o4 < 16; ++o4) {
                float4 cc = c4[o4], ss = s4[o4];
                acc[o4 * 4 + 0] += ck * cc.x + sk * ss.x;
                acc[o4 * 4 + 1] += ck * cc.y + sk * ss.y;
                acc[o4 * 4 + 2] += ck * cc.z + sk * ss.z;
                acc[o4 * 4 + 3] += ck * cc.w + sk * ss.w;
            }
        }
    }
#pragma unroll
    for (int o = 0; o < 64; ++o) tr[o * 129 + tid] = acc[o];
    __syncthreads();
    int e0 = blockIdx.x * 128;
#pragma unroll
    for (int o = 0; o < 64; ++o)
        g_h1T[o * NEDGE + e0 + tid] = tr[o * 129 + tid];
}

// ---------------- fp16x2 tensor-core fused-basis GEMM (layers 2,3) ----------
// D = (Ah + Al)  @ Bh : 2 HMMA streams; dropped term is only B's fp16 rounding.
__device__ __forceinline__ void mma_f16(float* c, uint32_t a0, uint32_t a1,
                                        uint32_t a2, uint32_t a3,
                                        uint32_t b0, uint32_t b1) {
    asm volatile(
        "mma.sync.aligned.m16n8k16.row.col.f32.f16.f16.f32 "
        "{%0,%1,%2,%3}, {%4,%5,%6,%7}, {%8,%9}, {%0,%1,%2,%3};\n"
        : "+f"(c[0]), "+f"(c[1]), "+f"(c[2]), "+f"(c[3])
        : "r"(a0), "r"(a1), "r"(a2), "r"(a3), "r"(b0), "r"(b1));
}

__device__ __forceinline__ uint32_t pack_h2(float lo, float hi) {
    __half2 h = __floats2half2_rn(lo, hi);
    return *(uint32_t*)&h;
}

template<int LAYER>
__global__ void __launch_bounds__(256, 2)
kan_mma(const float* __restrict__ bias) {
    constexpr int W    = (LAYER == 2) ? 16 : 32;
    constexpr int S    = (LAYER == 2) ? 8  : 16;
    constexpr int DOUT = (LAYER == 2) ? 128 : 1024;
    constexpr int M    = (LAYER == 2) ? NEDGE : NPTS;
    constexpr int COLS = 7 * W;          // 112 / 224
    constexpr int NCH  = COLS / 8;       // 14 / 28
    constexpr int KTOT = COLS * 10;      // 1120 / 2240
    constexpr int SA   = 88;             // padded k-stride (fp16 units)

    extern __shared__ unsigned char dynsm[];
    __half* sAh = (__half*)dynsm;
    __half* sAl = sAh + 128 * SA;
    __half* sBh = sAl + 128 * SA;

    const float* x = (LAYER == 2) ? g_h1T : g_x1T;     // [d][M]
    const __half* Bh = (LAYER == 2) ? g_B2 : g_B3;
    float* y = (LAYER == 2) ? g_y2 : g_x3;

    int m0 = blockIdx.x * 128;
    int n0 = blockIdx.y * 128;
    int tid = threadIdx.x;
    int lane = tid & 31, warp = tid >> 5;
    int wm = warp & 3, wn = warp >> 2;   // warp tile: 32 rows x 64 cols
    int qr = lane >> 2, qk = lane & 3;
    int row = tid & 127, cg = tid >> 7;  // producer: row + col-group (4 cols each)

    float acc[2][8][4];
#pragma unroll
    for (int m = 0; m < 2; ++m)
#pragma unroll
        for (int n = 0; n < 8; ++n)
#pragma unroll
            for (int q = 0; q < 4; ++q) acc[m][n][q] = 0.f;

    for (int ch = 0; ch < NCH; ++ch) {
        __syncthreads();
        // ---- produce A: all 256 threads, 4 cols each (128 rows x 8 cols) ----
#pragma unroll
        for (int cc = 0; cc < 4; ++cc) {
            int cl = cg * 4 + cc;            // col 0..7 within chunk
            int col = ch * 8 + cl;
            int w = col / W, i = col - w * W;
            float ham = 0.54f - 0.46f * cosf(6.2831853071795864f * (float)i / (float)(W - 1));
            float a = x[(size_t)(w * S + i) * M + m0 + row] * ham;
            float s, c; __sincosf(a, &s, &c);
            float ck = c, sk = s;
            uint32_t* ph = (uint32_t*)&sAh[row * SA + cl * 10];
            uint32_t* pl = (uint32_t*)&sAl[row * SA + cl * 10];
#pragma unroll
            for (int k = 0; k < 5; ++k) {
                if (k > 0) { float cn = ck * c - sk * s, sn = sk * c + ck * s; ck = cn; sk = sn; }
                __half chh = __float2half_rn(ck);
                __half shh = __float2half_rn(sk);
                ph[k] = pack_h2(ck, sk);     // rn to fp16 pair (cos, sin)
                pl[k] = pack_h2(ck - __half2float(chh), sk - __half2float(shh));
            }
        }
        // ---- stage B: warps 0-3, one n-row each (80 fp16 = 10 uint4) ----
        if (tid < 128) {
            const uint4* gb = (const uint4*)(Bh + (size_t)(n0 + tid) * KTOT + ch * 80);
            uint4* sp = (uint4*)(sBh + tid * SA);
#pragma unroll
            for (int q = 0; q < 10; ++q) sp[q] = gb[q];
        }
        __syncthreads();

#pragma unroll
        for (int ks = 0; ks < 5; ++ks) {
            int kb = ks * 16;
            uint32_t ah[2][4], al[2][4];
#pragma unroll
            for (int m = 0; m < 2; ++m) {
                int rb = (wm * 32 + m * 16 + qr) * SA + kb + qk * 2;
                ah[m][0] = *(const uint32_t*)&sAh[rb];
                ah[m][1] = *(const uint32_t*)&sAh[rb + 8 * SA];
                ah[m][2] = *(const uint32_t*)&sAh[rb + 8];
                ah[m][3] = *(const uint32_t*)&sAh[rb + 8 * SA + 8];
                al[m][0] = *(const uint32_t*)&sAl[rb];
                al[m][1] = *(const uint32_t*)&sAl[rb + 8 * SA];
                al[m][2] = *(const uint32_t*)&sAl[rb + 8];
                al[m][3] = *(const uint32_t*)&sAl[rb + 8 * SA + 8];
            }
#pragma unroll
            for (int n = 0; n < 8; ++n) {
                int bb = (wn * 64 + n * 8 + qr) * SA + kb + qk * 2;
                uint32_t bh0 = *(const uint32_t*)&sBh[bb];
                uint32_t bh1 = *(const uint32_t*)&sBh[bb + 8];
#pragma unroll
                for (int m = 0; m < 2; ++m) {
                    mma_f16(acc[m][n], ah[m][0], ah[m][1], ah[m][2], ah[m][3], bh0, bh1);
                    mma_f16(acc[m][n], al[m][0], al[m][1], al[m][2], al[m][3], bh0, bh1);
                }
            }
        }
    }

    // epilogue
#pragma unroll
    for (int m = 0; m < 2; ++m) {
        int r0 = m0 + wm * 32 + m * 16 + qr;
#pragma unroll
        for (int n = 0; n < 8; ++n) {
            int c0 = n0 + wn * 64 + n * 8 + qk * 2;
            float bv0 = bias[c0], bv1 = bias[c0 + 1];
            float2 v0 = make_float2(acc[m][n][0] + bv0, acc[m][n][1] + bv1);
            float2 v1 = make_float2(acc[m][n][2] + bv0, acc[m][n][3] + bv1);
            *(float2*)&y[(size_t)r0 * DOUT + c0] = v0;
            *(float2*)&y[(size_t)(r0 + 8) * DOUT + c0] = v1;
        }
    }
}

// ---------------- max over K neighbors, transposed output -------------------
__global__ void maxagg_kernel() {
    extern __shared__ unsigned char dynsm[];
    float* s = (float*)dynsm;               // [128][133]
    int n0 = blockIdx.x * 128;
    for (int idx = threadIdx.x; idx < 128 * 128; idx += 256) {
        int p = idx >> 7, c = idx & 127;
        const float* src = g_y2 + ((size_t)(n0 + p) * KNN) * 128 + c;
        float m = src[0];
#pragma unroll
        for (int j = 1; j < KNN; ++j) m = fmaxf(m, src[j * 128]);
        s[c * 133 + p] = m;
    }
    __syncthreads();
    for (int idx = threadIdx.x; idx < 128 * 128; idx += 256) {
        int c = idx >> 7, p = idx & 127;
        g_x1T[(size_t)c * NPTS + n0 + p] = s[c * 133 + p];
    }
}

// ---------------- segment max + mean pooling ----------------
__global__ void pool_kernel() {
    int b = blockIdx.x;
    int c = blockIdx.y * 128 + threadIdx.x;
    const float* p = g_x3 + (size_t)b * PPC * 1024 + c;
    float mx = -1e30f, sm = 0.f;
    for (int pt = 0; pt < PPC; ++pt) {
        float v = p[(size_t)pt * 1024];
        mx = fmaxf(mx, v); sm += v;
    }
    g_xg[b * 2048 + c] = mx;
    g_xg[b * 2048 + 1024 + c] = sm * (1.0f / 1024.0f);
}

// ---------------- layer4 ----------------
__global__ void layer4_part() {
    __shared__ float xs[2048];
    __shared__ float wsum[8][40];
    int b = blockIdx.x, sl = blockIdx.y, tid = threadIdx.x;
    for (int i = tid; i < 2048; i += 256) xs[i] = g_xg[b * 2048 + i];
    __syncthreads();
    float acc[40];
#pragma unroll
    for (int o = 0; o < 40; ++o) acc[o] = 0.f;
    for (int pp = tid; pp < 480; pp += 256) {
        int p = sl * 480 + pp;
        int w = p >> 8, i = p & 255;
        int d = (w << 7) + i;
        float ham = 0.54f - 0.46f * cosf(6.2831853071795864f * (float)i / 255.0f);
        float a = xs[d] * ham;
        float s, c; __sincosf(a, &s, &c);
        float ck = c, sk = s;
        const float* bp = g_Bp4 + p * 400;
#pragma unroll
        for (int k = 0; k < 5; ++k) {
            if (k > 0) { float cn = ck * c - sk * s, sn = sk * c + ck * s; ck = cn; sk = sn; }
            const float* c0 = bp + (2 * k) * 40;
            const float* s0 = bp + (2 * k + 1) * 40;
#pragma unroll
            for (int o = 0; o < 40; ++o) acc[o] += ck * c0[o] + sk * s0[o];
        }
    }
    int lane = tid & 31, wp = tid >> 5;
#pragma unroll
    for (int o = 0; o < 40; ++o) {
        float t = acc[o];
#pragma unroll
        for (int off = 16; off > 0; off >>= 1) t += __shfl_down_sync(0xffffffffu, t, off);
        if (lane == 0) wsum[wp][o] = t;
    }
    __syncthreads();
    if (tid < 40) {
        float t = 0.f;
#pragma unroll
        for (int w8 = 0; w8 < 8; ++w8) t += wsum[w8][tid];
        g_l4p[(b * 8 + sl) * 40 + tid] = t;
    }
}

__global__ void layer4_final(const float* __restrict__ b4, float* __restrict__ out) {
    int t = threadIdx.x;
    if (t < 320) {
        int o = t % 40;
        int b = t / 40;
        float s = b4[o];
#pragma unroll
        for (int sl = 0; sl < 8; ++sl) s += g_l4p[(b * 8 + sl) * 40 + o];
        out[t] = s;
    }
}

// ---------------- launch ----------------
extern "C" void kernel_launch(void* const* d_in, const int* in_sizes, int n_in,
                              void* d_out, int out_size) {
    (void)in_sizes; (void)n_in; (void)out_size;
    const float* pos = (const float*)d_in[0];
    const float* c1  = (const float*)d_in[2];
    const float* b1  = (const float*)d_in[3];
    const float* c2  = (const float*)d_in[4];
    const float* b2  = (const float*)d_in[5];
    const float* c3  = (const float*)d_in[6];
    const float* b3  = (const float*)d_in[7];
    const float* c4  = (const float*)d_in[8];
    const float* b4  = (const float*)d_in[9];
    float* out = (float*)d_out;

    const int SM_MMA = 3 * 128 * 88 * 2;        // 67584 B (Ah, Al, Bh)
    const int SM_MAX = 128 * 133 * 4;           // 68096 B
    cudaFuncSetAttribute(kan_mma<2>, cudaFuncAttributeMaxDynamicSharedMemorySize, SM_MMA);
    cudaFuncSetAttribute(kan_mma<3>, cudaFuncAttributeMaxDynamicSharedMemorySize, SM_MMA);
    cudaFuncSetAttribute(maxagg_kernel, cudaFuncAttributeMaxDynamicSharedMemorySize, SM_MAX);

    knn_kernel<<<32, 256>>>(pos);                                   // 0
    pack_fp16<<<560, 256>>>(c2, 0, 128, 16, 128 * 1120);            // 1
    layer1_kernel<<<NEDGE / 128, 128>>>(pos, c1, b1);               // 2
    kan_mma<2><<<dim3(NEDGE / 128, 1), 256, SM_MMA>>>(b2);          // 3  <- ncu slot
    maxagg_kernel<<<NPTS / 128, 256, SM_MAX>>>();                   // 4
    pack_fp16<<<4096, 256>>>(c3, 1, 1024, 32, 1024 * 2240);         // 5
    kan_mma<3><<<dim3(NPTS / 128, 8), 256, SM_MMA>>>(b3);           // 6
    pack_coef4<<<6000, 256>>>(c4);                                  // 7
    pool_kernel<<<dim3(NB, 8), 128>>>();                            // 8
    layer4_part<<<dim3(NB, 8), 256>>>();                            // 9
    layer4_final<<<1, 320>>>(b4, out);                              // 10
}